// round 2
// baseline (speedup 1.0000x reference)
#include <cuda_runtime.h>
#include <cuda_bf16.h>

// Problem constants
#define NROWS 16384   // B*S
#define KDIM  512     // H
#define NCOLS 640     // G*V
#define VDIM  320     // V (= group width GN)
#define DG    128     // D/G
#define GN    320
#define KT    16
#define M_TILE 64
#define OUT_ELEMS (NROWS * 256)  // B*S*D

__device__ float g_marginal[NCOLS];

// ---------------------------------------------------------------------------
// Kernel 0: zero the marginal accumulator (graph is replayed; must reset)
// ---------------------------------------------------------------------------
__global__ void zero_marg_kernel() {
    g_marginal[threadIdx.x] = 0.0f;
}

// ---------------------------------------------------------------------------
// Fused kernel: GEMM (64 x 320 x 512 tiles) + bias + argmax(logit+gumbel)
// + softmax(logit) + masked marginal accumulation + codevector gather.
// Grid: (NROWS/64, 2 groups). 256 threads; microtile 8(M) x 10(N).
// Thread map: tx = tid&31 (cols tx+32j), ty = tid>>5 (rows ty*8+i).
// Each warp owns 8 full rows -> warp-level argmax/softmax reductions.
// ---------------------------------------------------------------------------
__global__ __launch_bounds__(256)
void fused_kernel(const float* __restrict__ X,
                  const float* __restrict__ W,
                  const float* __restrict__ bias,
                  const float* __restrict__ gum,
                  const int*   __restrict__ mask,
                  const float* __restrict__ cb,
                  float* __restrict__ out) {
    __shared__ float As[2][KT][M_TILE];   // [k][m]
    __shared__ float Bs[2][KT][GN];       // [k][n]
    float* smarg = &Bs[0][0][0];          // reused after main loop (320 floats)

    const int tid = threadIdx.x;
    const int m0  = blockIdx.x * M_TILE;
    const int g   = blockIdx.y;
    const int g0  = g * GN;
    const int tx  = tid & 31;
    const int ty  = tid >> 5;

    // ---- global load mappings ----
    // A: one float4 per thread per k-tile
    const int am = tid >> 2;            // 0..63
    const int ak = (tid & 3) * 4;       // 0,4,8,12
    const float* Aptr = X + (size_t)(m0 + am) * KDIM + ak;

    // B: five float4 per thread per k-tile (16x320 = 1280 float4)
    int bkj[5], bnj[5];
    #pragma unroll
    for (int j = 0; j < 5; j++) {
        const int idx = tid + 256 * j;
        bkj[j] = idx / 80;
        bnj[j] = (idx % 80) * 4;
    }
    const float* Bptr = W + g0;

    // ---- preload tile 0 ----
    float4 a_pf = *(const float4*)(Aptr);
    float4 b_pf[5];
    #pragma unroll
    for (int j = 0; j < 5; j++)
        b_pf[j] = *(const float4*)(Bptr + (size_t)bkj[j] * NCOLS + bnj[j]);

    As[0][ak + 0][am] = a_pf.x;
    As[0][ak + 1][am] = a_pf.y;
    As[0][ak + 2][am] = a_pf.z;
    As[0][ak + 3][am] = a_pf.w;
    #pragma unroll
    for (int j = 0; j < 5; j++)
        *(float4*)&Bs[0][bkj[j]][bnj[j]] = b_pf[j];
    __syncthreads();

    float acc[8][10];
    #pragma unroll
    for (int i = 0; i < 8; i++)
        #pragma unroll
        for (int j = 0; j < 10; j++) acc[i][j] = 0.0f;

    const int KTILES = KDIM / KT;  // 32
    for (int kt = 0; kt < KTILES; kt++) {
        const int cur = kt & 1;
        const int nxt = cur ^ 1;

        if (kt < KTILES - 1) {
            const float* Ap = Aptr + (kt + 1) * KT;
            const float* Bp = Bptr + (size_t)(kt + 1) * KT * NCOLS;
            a_pf = *(const float4*)(Ap);
            #pragma unroll
            for (int j = 0; j < 5; j++)
                b_pf[j] = *(const float4*)(Bp + (size_t)bkj[j] * NCOLS + bnj[j]);
        }

        #pragma unroll
        for (int k = 0; k < KT; k++) {
            float ar[8], br[10];
            *(float4*)(ar)     = *(const float4*)&As[cur][k][ty * 8];      // broadcast
            *(float4*)(ar + 4) = *(const float4*)&As[cur][k][ty * 8 + 4];  // broadcast
            #pragma unroll
            for (int j = 0; j < 10; j++) br[j] = Bs[cur][k][tx + 32 * j];  // conflict-free
            #pragma unroll
            for (int i = 0; i < 8; i++)
                #pragma unroll
                for (int j = 0; j < 10; j++)
                    acc[i][j] = fmaf(ar[i], br[j], acc[i][j]);
        }

        if (kt < KTILES - 1) {
            As[nxt][ak + 0][am] = a_pf.x;
            As[nxt][ak + 1][am] = a_pf.y;
            As[nxt][ak + 2][am] = a_pf.z;
            As[nxt][ak + 3][am] = a_pf.w;
            #pragma unroll
            for (int j = 0; j < 5; j++)
                *(float4*)&Bs[nxt][bkj[j]][bnj[j]] = b_pf[j];
            __syncthreads();
        }
    }

    // ---- epilogue ----
    __syncthreads();                               // done reading Bs; reuse as smarg
    for (int j = tid; j < GN; j += 256) smarg[j] = 0.0f;
    __syncthreads();

    float bcol[10];
    #pragma unroll
    for (int j = 0; j < 10; j++) bcol[j] = bias[g0 + tx + 32 * j];

    #pragma unroll
    for (int i = 0; i < 8; i++) {
        const int n = m0 + ty * 8 + i;
        const float* grow = gum + ((size_t)n * 2 + g) * GN;

        float l[10];
        float lmax = -1e30f, gmax = -1e30f;
        int   gidx = 0;
        #pragma unroll
        for (int j = 0; j < 10; j++) {
            l[j] = acc[i][j] + bcol[j];
            const float gv = l[j] + grow[tx + 32 * j];
            lmax = fmaxf(lmax, l[j]);
            if (gv > gmax) { gmax = gv; gidx = tx + 32 * j; }
        }
        // warp-reduce max of logits (for softmax)
        #pragma unroll
        for (int o = 16; o > 0; o >>= 1)
            lmax = fmaxf(lmax, __shfl_xor_sync(0xffffffffu, lmax, o));
        // warp-reduce argmax of logit+gumbel, ties -> lowest index (jnp.argmax)
        #pragma unroll
        for (int o = 16; o > 0; o >>= 1) {
            const float ov = __shfl_xor_sync(0xffffffffu, gmax, o);
            const int   oi = __shfl_xor_sync(0xffffffffu, gidx, o);
            if (ov > gmax || (ov == gmax && oi < gidx)) { gmax = ov; gidx = oi; }
        }
        // softmax of raw logits
        float e[10], s = 0.0f;
        #pragma unroll
        for (int j = 0; j < 10; j++) { e[j] = __expf(l[j] - lmax); s += e[j]; }
        #pragma unroll
        for (int o = 16; o > 0; o >>= 1)
            s += __shfl_xor_sync(0xffffffffu, s, o);
        const float inv = 1.0f / s;

        if (mask[n] != 0) {
            #pragma unroll
            for (int j = 0; j < 10; j++)
                atomicAdd(&smarg[tx + 32 * j], e[j] * inv);
        }

        // gather selected codevector row: 128 floats = 32 float4 per warp
        const float4* cbr = (const float4*)(cb + (size_t)(g0 + gidx) * DG);
        float4* o4 = (float4*)(out + (size_t)n * 256 + g * DG);
        o4[tx] = cbr[tx];
    }

    __syncthreads();
    for (int j = tid; j < GN; j += 256)
        atomicAdd(&g_marginal[g0 + j], smarg[j]);
}

// ---------------------------------------------------------------------------
// Finalize: perplexity. One CTA, 640 threads = 20 warps.
// Warps 0-9 cover cols 0..319 (group 0), warps 10-19 cover group 1.
// ---------------------------------------------------------------------------
__global__ void finalize_kernel(const int* __restrict__ mask,
                                float* __restrict__ out, int out_size) {
    __shared__ float wsum[20];
    __shared__ float s_msum;
    const int tid  = threadIdx.x;
    const int warp = tid >> 5;
    const int lane = tid & 31;

    // masked-count reduction
    float c = 0.0f;
    for (int i = tid; i < NROWS; i += NCOLS) c += (mask[i] != 0) ? 1.0f : 0.0f;
    #pragma unroll
    for (int o = 16; o > 0; o >>= 1) c += __shfl_xor_sync(0xffffffffu, c, o);
    if (lane == 0) wsum[warp] = c;
    __syncthreads();
    if (tid == 0) {
        float s = 0.0f;
        #pragma unroll
        for (int w = 0; w < 20; w++) s += wsum[w];
        s_msum = s;
    }
    __syncthreads();

    // entropy contributions
    const float p = g_marginal[tid] / s_msum;
    float h = p * logf(p + 1e-7f);
    #pragma unroll
    for (int o = 16; o > 0; o >>= 1) h += __shfl_xor_sync(0xffffffffu, h, o);
    __syncthreads();
    if (lane == 0) wsum[warp] = h;
    __syncthreads();

    if (tid == 0) {
        float e0 = 0.0f, e1 = 0.0f;
        #pragma unroll
        for (int w = 0; w < 10; w++)  e0 += wsum[w];
        #pragma unroll
        for (int w = 10; w < 20; w++) e1 += wsum[w];
        const float perp = expf(-e0) + expf(-e1);
        if (out_size > OUT_ELEMS) out[OUT_ELEMS] = perp;
    }
}

// ---------------------------------------------------------------------------
extern "C" void kernel_launch(void* const* d_in, const int* in_sizes, int n_in,
                              void* d_out, int out_size) {
    const float* X    = (const float*)d_in[0];  // hidden_states [8,2048,512]
    const int*   mask = (const int*)  d_in[1];  // mask_time_indices [8,2048]
    const float* W    = (const float*)d_in[2];  // W_proj [512,640]
    const float* b    = (const float*)d_in[3];  // b_proj [640]
    const float* cb   = (const float*)d_in[4];  // codevectors [1,640,128]
    const float* gum  = (const float*)d_in[5];  // gumbels [32768,320]
    float* out = (float*)d_out;

    zero_marg_kernel<<<1, NCOLS>>>();
    dim3 fgrid(NROWS / M_TILE, 2);              // (256, 2)
    fused_kernel<<<fgrid, 256>>>(X, W, b, gum, mask, cb, out);
    finalize_kernel<<<1, NCOLS>>>(mask, out, out_size);
}

// round 8
// speedup vs baseline: 1.1861x; 1.1861x over previous
#include <cuda_runtime.h>
#include <cuda_bf16.h>
#include <cstdint>

// Problem constants
#define NROWS 16384   // B*S
#define KDIM  512     // H
#define NCOLS 640     // G*V
#define VDIM  320
#define DG    128
#define OUT_ELEMS (NROWS * 256)

// ---------------- device globals ----------------
__device__ __nv_bfloat16 g_Xs[3][NROWS * KDIM];   // 3 x 16 MB split of X
__device__ __nv_bfloat16 g_Wt[3][NCOLS * KDIM];   // 3 x 0.65 MB split of W^T
__device__ float g_logits[NROWS * NCOLS];         // 42 MB (bias included)
__device__ float g_marginal[NCOLS];

// ---------------- PTX helpers (compute_103-legal only) ----------------
__device__ __forceinline__ uint32_t smem_to_u32(const void* p) {
    uint32_t a;
    asm("{ .reg .u64 t; cvta.to.shared.u64 t, %1; cvt.u32.u64 %0, t; }" : "=r"(a) : "l"(p));
    return a;
}
__device__ __forceinline__ void ldmx4(uint32_t* r, uint32_t addr) {
    asm volatile("ldmatrix.sync.aligned.m8n8.x4.shared.b16 {%0,%1,%2,%3}, [%4];"
                 : "=r"(r[0]), "=r"(r[1]), "=r"(r[2]), "=r"(r[3]) : "r"(addr));
}
__device__ __forceinline__ void mma16816(float* c, const uint32_t* a,
                                         uint32_t b0, uint32_t b1) {
    asm volatile("mma.sync.aligned.m16n8k16.row.col.f32.bf16.bf16.f32 "
                 "{%0,%1,%2,%3}, {%4,%5,%6,%7}, {%8,%9}, {%0,%1,%2,%3};"
                 : "+f"(c[0]), "+f"(c[1]), "+f"(c[2]), "+f"(c[3])
                 : "r"(a[0]), "r"(a[1]), "r"(a[2]), "r"(a[3]), "r"(b0), "r"(b1));
}
#define SWZ128(off) ((off) ^ (((off) >> 3) & 0x70))

// ---------------------------------------------------------------------------
// Prep: split W (transposed) into 3 bf16 terms.
// ---------------------------------------------------------------------------
__global__ void split_w_kernel(const float* __restrict__ W) {
    const int t = blockIdx.x * 256 + threadIdx.x;
    if (t >= KDIM * NCOLS) return;
    const int k = t / NCOLS, n = t % NCOLS;
    const float x = W[t];
    const __nv_bfloat16 b0 = __float2bfloat16(x);
    const float r1 = x - __bfloat162float(b0);
    const __nv_bfloat16 b1 = __float2bfloat16(r1);
    const float r2 = r1 - __bfloat162float(b1);
    const __nv_bfloat16 b2 = __float2bfloat16(r2);
    const size_t o = (size_t)n * KDIM + k;
    g_Wt[0][o] = b0; g_Wt[1][o] = b1; g_Wt[2][o] = b2;
}

// ---------------------------------------------------------------------------
// Prep: split X into 3 bf16 terms, 8 elems/thread.
// ---------------------------------------------------------------------------
__global__ __launch_bounds__(256)
void split_x_kernel(const float* __restrict__ X) {
    const size_t base = ((size_t)blockIdx.x * 256 + threadIdx.x) * 8;
    const float4 x0 = *(const float4*)(X + base);
    const float4 x1 = *(const float4*)(X + base + 4);
    const float xs[8] = {x0.x, x0.y, x0.z, x0.w, x1.x, x1.y, x1.z, x1.w};
    __nv_bfloat16 s0[8], s1[8], s2[8];
    #pragma unroll
    for (int i = 0; i < 8; i++) {
        const float x = xs[i];
        s0[i] = __float2bfloat16(x);
        const float r1 = x - __bfloat162float(s0[i]);
        s1[i] = __float2bfloat16(r1);
        const float r2 = r1 - __bfloat162float(s1[i]);
        s2[i] = __float2bfloat16(r2);
    }
    *(uint4*)(&g_Xs[0][base]) = *(uint4*)s0;
    *(uint4*)(&g_Xs[1][base]) = *(uint4*)s1;
    *(uint4*)(&g_Xs[2][base]) = *(uint4*)s2;
}

__global__ void zero_marg_kernel() { g_marginal[threadIdx.x] = 0.0f; }

// ---------------------------------------------------------------------------
// bf16x6 GEMM via mma.sync: logits = X @ W + b, fp32-accurate.
// CTA tile 128M x 160N; K' = 6*512 = 3072 (48 chunks of 64).
// 8 warps as 4M x 2N; warp tile 32M x 80N; 256 threads.
// Grid (4, 128): blockIdx.x = N tile, blockIdx.y = M tile.
// ---------------------------------------------------------------------------
#define SM_A_SZ 16384   // 128 x 64 bf16
#define SM_B_SZ 20480   // 160 x 64 bf16
#define GEMM_SMEM (2 * SM_A_SZ + 2 * SM_B_SZ)  // 73728

__global__ __launch_bounds__(256, 1)
void gemm_kernel(const float* __restrict__ bias) {
    extern __shared__ char smem[];
    const uint32_t sA = smem_to_u32(smem);             // 2 x 16KB
    const uint32_t sB = sA + 2 * SM_A_SZ;              // 2 x 20KB

    const int tid  = threadIdx.x;
    const int lane = tid & 31;
    const int warp = tid >> 5;
    const int wm   = warp >> 1;        // 0..3
    const int wn   = warp & 1;         // 0..1
    const int m0   = blockIdx.y * 128;
    const int n0   = blockIdx.x * 160;

    // ---- LDG/STS mappings ----
    int arow[4], acol[4], asts[4];
    #pragma unroll
    for (int j = 0; j < 4; j++) {
        const int u = tid + 256 * j;
        arow[j] = u >> 3; acol[j] = u & 7;
        asts[j] = SWZ128(arow[j] * 128 + acol[j] * 16);
    }
    int brow[5], bcol[5], bsts[5];
    #pragma unroll
    for (int j = 0; j < 5; j++) {
        const int u = tid + 256 * j;
        brow[j] = u >> 3; bcol[j] = u & 7;
        bsts[j] = SWZ128(brow[j] * 128 + bcol[j] * 16);
    }

    // ---- ldmatrix per-lane address components ----
    uint32_t a_rb[2], a_sw[2];
    #pragma unroll
    for (int i = 0; i < 2; i++) {
        const int r = wm * 32 + i * 16 + (lane & 15);
        a_rb[i] = (uint32_t)(r * 128);
        a_sw[i] = (uint32_t)((r & 7) << 4);
    }
    const uint32_t a_kc = (uint32_t)((lane >> 4) << 4);
    uint32_t b_rb[5], b_sw[5];
    #pragma unroll
    for (int j = 0; j < 5; j++) {
        const int n = wn * 80 + j * 16 + (lane & 7) + ((lane >> 4) << 3);
        b_rb[j] = (uint32_t)(n * 128);
        b_sw[j] = (uint32_t)((n & 7) << 4);
    }
    const uint32_t b_kc = (uint32_t)(((lane >> 3) & 1) << 4);

    float acc[2][10][4];
    #pragma unroll
    for (int i = 0; i < 2; i++)
        #pragma unroll
        for (int j = 0; j < 10; j++)
            #pragma unroll
            for (int q = 0; q < 4; q++) acc[i][j][q] = 0.0f;

    uint4 aR[4], bR[5];

    // prologue: step 0 (sa=0, sb=0, kc=0)
    #pragma unroll
    for (int j = 0; j < 4; j++)
        aR[j] = *(const uint4*)(&g_Xs[0][(size_t)(m0 + arow[j]) * KDIM + acol[j] * 8]);
    #pragma unroll
    for (int j = 0; j < 5; j++)
        bR[j] = *(const uint4*)(&g_Wt[0][(size_t)(n0 + brow[j]) * KDIM + bcol[j] * 8]);
    #pragma unroll
    for (int j = 0; j < 4; j++) *(uint4*)(smem + asts[j]) = aR[j];
    #pragma unroll
    for (int j = 0; j < 5; j++) *(uint4*)(smem + 2 * SM_A_SZ + bsts[j]) = bR[j];
    __syncthreads();

    int abuf = 0;
    for (int s = 0; s < 48; s++) {
        const int bbuf = s & 1;
        const int s2 = s + 1;
        const bool haveNext = (s2 < 48);
        const int kc2 = s2 / 6, jj2 = s2 % 6;
        const bool newA2 = (jj2 == 0 || jj2 == 3 || jj2 == 5);
        const int sa2 = (jj2 < 3) ? 0 : (jj2 < 5 ? 1 : 2);
        const int sb2 = (jj2 < 3) ? jj2 : (jj2 < 5 ? jj2 - 3 : 0);

        // LDG next step (latency overlapped with compute below)
        if (haveNext) {
            if (newA2) {
                const __nv_bfloat16* Ap = g_Xs[sa2];
                #pragma unroll
                for (int j = 0; j < 4; j++)
                    aR[j] = *(const uint4*)(&Ap[(size_t)(m0 + arow[j]) * KDIM + kc2 * 64 + acol[j] * 8]);
            }
            const __nv_bfloat16* Bp = g_Wt[sb2];
            #pragma unroll
            for (int j = 0; j < 5; j++)
                bR[j] = *(const uint4*)(&Bp[(size_t)(n0 + brow[j]) * KDIM + kc2 * 64 + bcol[j] * 8]);
        }

        // compute chunk (4 x k16)
        {
            const uint32_t aBase = sA + abuf * SM_A_SZ;
            const uint32_t bBase = sB + bbuf * SM_B_SZ;
            #pragma unroll
            for (int ks = 0; ks < 4; ks++) {
                const uint32_t k2 = (uint32_t)(ks * 32);
                uint32_t af[2][4], bf[5][4];
                #pragma unroll
                for (int i = 0; i < 2; i++)
                    ldmx4(af[i], aBase + a_rb[i] + ((k2 + a_kc) ^ a_sw[i]));
                #pragma unroll
                for (int j = 0; j < 5; j++)
                    ldmx4(bf[j], bBase + b_rb[j] + ((k2 + b_kc) ^ b_sw[j]));
                #pragma unroll
                for (int i = 0; i < 2; i++)
                    #pragma unroll
                    for (int j = 0; j < 5; j++) {
                        mma16816(acc[i][2 * j],     af[i], bf[j][0], bf[j][1]);
                        mma16816(acc[i][2 * j + 1], af[i], bf[j][2], bf[j][3]);
                    }
            }
        }

        // STS next step into opposite buffers; their previous readers passed
        // the prior __syncthreads, so overwrite is safe.
        if (haveNext) {
            if (newA2) {
                char* ab = smem + (abuf ^ 1) * SM_A_SZ;
                #pragma unroll
                for (int j = 0; j < 4; j++) *(uint4*)(ab + asts[j]) = aR[j];
            }
            char* bb = smem + 2 * SM_A_SZ + (bbuf ^ 1) * SM_B_SZ;
            #pragma unroll
            for (int j = 0; j < 5; j++) *(uint4*)(bb + bsts[j]) = bR[j];
        }
        __syncthreads();
        if (haveNext && newA2) abuf ^= 1;
    }

    // ---- epilogue: add bias, store to g_logits ----
    #pragma unroll
    for (int j = 0; j < 10; j++) {
        const int col = n0 + wn * 80 + j * 8 + (lane & 3) * 2;
        const float2 bb = *(const float2*)(bias + col);
        #pragma unroll
        for (int i = 0; i < 2; i++) {
            const int r0 = m0 + wm * 32 + i * 16 + (lane >> 2);
            float2 v0 = { acc[i][j][0] + bb.x, acc[i][j][1] + bb.y };
            float2 v1 = { acc[i][j][2] + bb.x, acc[i][j][3] + bb.y };
            *(float2*)(&g_logits[(size_t)r0 * NCOLS + col])       = v0;
            *(float2*)(&g_logits[(size_t)(r0 + 8) * NCOLS + col]) = v1;
        }
    }
}

// ---------------------------------------------------------------------------
// Row kernel (proven in R1): argmax(l+gumbel) + softmax(l) + marginal + gather
// ---------------------------------------------------------------------------
__global__ __launch_bounds__(256)
void row_kernel(const float* __restrict__ gumbels,
                const int*   __restrict__ mask,
                const float* __restrict__ codevectors,
                float* __restrict__ out) {
    __shared__ float smarg[NCOLS];
    const int tid = threadIdx.x;
    for (int j = tid; j < NCOLS; j += 256) smarg[j] = 0.0f;
    __syncthreads();

    const int warp = tid >> 5;
    const int lane = tid & 31;
    const int g = warp & 1;
    const int nbase = blockIdx.x * 16 + (warp >> 1) * 4;

    for (int r = 0; r < 4; r++) {
        const int n = nbase + r;
        const float* lrow = g_logits + (size_t)n * NCOLS + g * VDIM;
        const float* grow = gumbels  + (size_t)n * NCOLS + g * VDIM;

        float l[10];
        float lmax = -1e30f, gmax = -1e30f;
        int gidx = 0;
        #pragma unroll
        for (int i = 0; i < 10; i++) {
            const int v = lane + 32 * i;
            l[i] = lrow[v];
            const float gv = l[i] + grow[v];
            lmax = fmaxf(lmax, l[i]);
            if (gv > gmax) { gmax = gv; gidx = v; }
        }
        #pragma unroll
        for (int o = 16; o > 0; o >>= 1)
            lmax = fmaxf(lmax, __shfl_xor_sync(0xffffffffu, lmax, o));
        #pragma unroll
        for (int o = 16; o > 0; o >>= 1) {
            const float ov = __shfl_xor_sync(0xffffffffu, gmax, o);
            const int   oi = __shfl_xor_sync(0xffffffffu, gidx, o);
            if (ov > gmax || (ov == gmax && oi < gidx)) { gmax = ov; gidx = oi; }
        }
        float e[10], s = 0.0f;
        #pragma unroll
        for (int i = 0; i < 10; i++) { e[i] = __expf(l[i] - lmax); s += e[i]; }
        #pragma unroll
        for (int o = 16; o > 0; o >>= 1)
            s += __shfl_xor_sync(0xffffffffu, s, o);
        const float inv = 1.0f / s;

        if (mask[n] != 0) {
            #pragma unroll
            for (int i = 0; i < 10; i++)
                atomicAdd(&smarg[g * VDIM + lane + 32 * i], e[i] * inv);
        }

        const float4* cb = (const float4*)(codevectors + (size_t)(g * VDIM + gidx) * DG);
        float4* o4 = (float4*)(out + (size_t)n * 256 + g * DG);
        o4[lane] = cb[lane];
    }

    __syncthreads();
    for (int j = tid; j < NCOLS; j += 256)
        atomicAdd(&g_marginal[j], smarg[j]);
}

// ---------------------------------------------------------------------------
// Finalize: perplexity (proven in R2). One CTA, 640 threads = 20 warps.
// ---------------------------------------------------------------------------
__global__ void finalize_kernel(const int* __restrict__ mask,
                                float* __restrict__ out, int out_size) {
    __shared__ float wsum[20];
    __shared__ float s_msum;
    const int tid  = threadIdx.x;
    const int warp = tid >> 5;
    const int lane = tid & 31;

    float c = 0.0f;
    for (int i = tid; i < NROWS; i += NCOLS) c += (mask[i] != 0) ? 1.0f : 0.0f;
    #pragma unroll
    for (int o = 16; o > 0; o >>= 1) c += __shfl_xor_sync(0xffffffffu, c, o);
    if (lane == 0) wsum[warp] = c;
    __syncthreads();
    if (tid == 0) {
        float s = 0.0f;
        #pragma unroll
        for (int w = 0; w < 20; w++) s += wsum[w];
        s_msum = s;
    }
    __syncthreads();

    const float p = g_marginal[tid] / s_msum;
    float h = p * logf(p + 1e-7f);
    #pragma unroll
    for (int o = 16; o > 0; o >>= 1) h += __shfl_xor_sync(0xffffffffu, h, o);
    __syncthreads();
    if (lane == 0) wsum[warp] = h;
    __syncthreads();

    if (tid == 0) {
        float e0 = 0.0f, e1 = 0.0f;
        #pragma unroll
        for (int w = 0; w < 10; w++)  e0 += wsum[w];
        #pragma unroll
        for (int w = 10; w < 20; w++) e1 += wsum[w];
        const float perp = expf(-e0) + expf(-e1);
        if (out_size > OUT_ELEMS) out[OUT_ELEMS] = perp;
    }
}

// ---------------------------------------------------------------------------
extern "C" void kernel_launch(void* const* d_in, const int* in_sizes, int n_in,
                              void* d_out, int out_size) {
    const float* X    = (const float*)d_in[0];
    const int*   mask = (const int*)  d_in[1];
    const float* W    = (const float*)d_in[2];
    const float* b    = (const float*)d_in[3];
    const float* cv   = (const float*)d_in[4];
    const float* gum  = (const float*)d_in[5];
    float* out = (float*)d_out;

    cudaFuncSetAttribute(gemm_kernel,
                         cudaFuncAttributeMaxDynamicSharedMemorySize, GEMM_SMEM);

    split_w_kernel<<<(KDIM * NCOLS + 255) / 256, 256>>>(W);
    split_x_kernel<<<NROWS * KDIM / (256 * 8), 256>>>(X);
    zero_marg_kernel<<<1, NCOLS>>>();
    dim3 ggrid(NCOLS / 160, NROWS / 128);   // (4, 128)
    gemm_kernel<<<ggrid, 256, GEMM_SMEM>>>(b);
    row_kernel<<<NROWS / 16, 256>>>(gum, mask, cv, out);
    finalize_kernel<<<1, NCOLS>>>(mask, out, out_size);
}

// round 15
// speedup vs baseline: 1.1950x; 1.0075x over previous
#include <cuda_runtime.h>
#include <cuda_bf16.h>
#include <cstdint>

// Problem constants
#define NROWS 16384   // B*S
#define KDIM  512     // H
#define KP    3072    // K' = 6*512 concatenated split dimension
#define NCOLS 640     // G*V
#define VDIM  320
#define DG    128
#define OUT_ELEMS (NROWS * 256)

// ---------------- device globals ----------------
// Concatenated split operands along K' (6 slots of 512):
//   slot s: A uses split sa[s], B uses split sb[s]
//   (sa,sb) = (0,0),(0,1),(1,0),(1,1),(0,2),(2,0)
__device__ __nv_bfloat16 g_Acat[NROWS * KP];   // 96 MB
__device__ __nv_bfloat16 g_Bcat[NCOLS * KP];   // 3.75 MB
__device__ float g_logits[NROWS * NCOLS];      // 42 MB (bias included)
__device__ float g_marginal[NCOLS];

// ---------------- PTX helpers (compute_103-legal only) ----------------
__device__ __forceinline__ uint32_t smem_to_u32(const void* p) {
    uint32_t a;
    asm("{ .reg .u64 t; cvta.to.shared.u64 t, %1; cvt.u32.u64 %0, t; }" : "=r"(a) : "l"(p));
    return a;
}
__device__ __forceinline__ void ldmx4(uint32_t* r, uint32_t addr) {
    asm volatile("ldmatrix.sync.aligned.m8n8.x4.shared.b16 {%0,%1,%2,%3}, [%4];"
                 : "=r"(r[0]), "=r"(r[1]), "=r"(r[2]), "=r"(r[3]) : "r"(addr));
}
__device__ __forceinline__ void mma16816(float* c, const uint32_t* a,
                                         uint32_t b0, uint32_t b1) {
    asm volatile("mma.sync.aligned.m16n8k16.row.col.f32.bf16.bf16.f32 "
                 "{%0,%1,%2,%3}, {%4,%5,%6,%7}, {%8,%9}, {%0,%1,%2,%3};"
                 : "+f"(c[0]), "+f"(c[1]), "+f"(c[2]), "+f"(c[3])
                 : "r"(a[0]), "r"(a[1]), "r"(a[2]), "r"(a[3]), "r"(b0), "r"(b1));
}
__device__ __forceinline__ void cp16(uint32_t sdst, const void* gsrc) {
    asm volatile("cp.async.cg.shared.global [%0], [%1], 16;"
                 :: "r"(sdst), "l"(gsrc) : "memory");
}
#define CP_COMMIT() asm volatile("cp.async.commit_group;" ::: "memory")
#define CP_WAIT1()  asm volatile("cp.async.wait_group 1;" ::: "memory")
#define SWZ128(off) ((off) ^ (((off) >> 3) & 0x70))

// ---------------------------------------------------------------------------
// Prep: split W into 3 bf16 terms, write concatenated B' rows.
// B' slot values: s0:w0 s1:w1 s2:w0 s3:w1 s4:w2 s5:w0
// ---------------------------------------------------------------------------
__global__ void split_w_kernel(const float* __restrict__ W) {
    const int t = blockIdx.x * 256 + threadIdx.x;
    if (t >= KDIM * NCOLS) return;
    const int k = t / NCOLS, n = t % NCOLS;
    const float x = W[t];
    const __nv_bfloat16 b0 = __float2bfloat16(x);
    const float r1 = x - __bfloat162float(b0);
    const __nv_bfloat16 b1 = __float2bfloat16(r1);
    const float r2 = r1 - __bfloat162float(b1);
    const __nv_bfloat16 b2 = __float2bfloat16(r2);
    __nv_bfloat16* row = g_Bcat + (size_t)n * KP + k;
    row[0]    = b0;  row[512]  = b1;  row[1024] = b0;
    row[1536] = b1;  row[2048] = b2;  row[2560] = b0;
}

// ---------------------------------------------------------------------------
// Prep: split X into 3 bf16 terms, write concatenated A' rows (8 elems/thread).
// A' slot values: s0:x0 s1:x0 s2:x1 s3:x1 s4:x0 s5:x2
// ---------------------------------------------------------------------------
__global__ __launch_bounds__(256)
void split_x_kernel(const float* __restrict__ X) {
    const size_t idx = (size_t)blockIdx.x * 256 + threadIdx.x;
    const size_t base = idx * 8;
    const int n = (int)(base / KDIM);
    const int k = (int)(base % KDIM);
    const float4 x0 = *(const float4*)(X + base);
    const float4 x1 = *(const float4*)(X + base + 4);
    const float xs[8] = {x0.x, x0.y, x0.z, x0.w, x1.x, x1.y, x1.z, x1.w};
    __nv_bfloat16 s0[8], s1[8], s2[8];
    #pragma unroll
    for (int i = 0; i < 8; i++) {
        const float x = xs[i];
        s0[i] = __float2bfloat16(x);
        const float r1 = x - __bfloat162float(s0[i]);
        s1[i] = __float2bfloat16(r1);
        const float r2 = r1 - __bfloat162float(s1[i]);
        s2[i] = __float2bfloat16(r2);
    }
    const uint4 v0 = *(uint4*)s0, v1 = *(uint4*)s1, v2 = *(uint4*)s2;
    __nv_bfloat16* row = g_Acat + (size_t)n * KP + k;
    *(uint4*)(row)        = v0;   // s0: x0
    *(uint4*)(row + 512)  = v0;   // s1: x0
    *(uint4*)(row + 1024) = v1;   // s2: x1
    *(uint4*)(row + 1536) = v1;   // s3: x1
    *(uint4*)(row + 2048) = v0;   // s4: x0
    *(uint4*)(row + 2560) = v2;   // s5: x2
}

__global__ void zero_marg_kernel() { g_marginal[threadIdx.x] = 0.0f; }

// ---------------------------------------------------------------------------
// Uniform K'=3072 GEMM via mma.sync + cp.async 3-stage pipeline.
// CTA tile 128M x 160N x 64K; 48 chunks. 8 warps as 4M x 2N (warp 32x80).
// Grid (4, 128). Explicit fragment double-buffering inside each chunk.
// ---------------------------------------------------------------------------
#define SM_A_SZ 16384            // 128 rows x 128 B
#define SM_B_SZ 20480            // 160 rows x 128 B
#define STAGE_SZ (SM_A_SZ + SM_B_SZ)      // 36864
#define GEMM_SMEM (3 * STAGE_SZ)          // 110592

__global__ __launch_bounds__(256, 1)
void gemm_kernel(const float* __restrict__ bias) {
    extern __shared__ char smem[];
    const uint32_t sBase = smem_to_u32(smem);

    const int tid  = threadIdx.x;
    const int lane = tid & 31;
    const int warp = tid >> 5;
    const int wm   = warp >> 1;        // 0..3
    const int wn   = warp & 1;         // 0..1
    const int m0   = blockIdx.y * 128;
    const int n0   = blockIdx.x * 160;

    // ---- cp.async src/dst mappings (16B units) ----
    const __nv_bfloat16* aSrc[4];
    uint32_t aDst[4];
    #pragma unroll
    for (int j = 0; j < 4; j++) {
        const int u = tid + 256 * j;
        const int row = u >> 3, col = u & 7;
        aSrc[j] = g_Acat + (size_t)(m0 + row) * KP + col * 8;
        aDst[j] = (uint32_t)SWZ128(row * 128 + col * 16);
    }
    const __nv_bfloat16* bSrc[5];
    uint32_t bDst[5];
    #pragma unroll
    for (int j = 0; j < 5; j++) {
        const int u = tid + 256 * j;
        const int row = u >> 3, col = u & 7;
        bSrc[j] = g_Bcat + (size_t)(n0 + row) * KP + col * 8;
        bDst[j] = (uint32_t)SWZ128(row * 128 + col * 16) + SM_A_SZ;
    }

    // ---- ldmatrix per-lane address components ----
    uint32_t a_rb[2], a_sw[2];
    #pragma unroll
    for (int i = 0; i < 2; i++) {
        const int r = wm * 32 + i * 16 + (lane & 15);
        a_rb[i] = (uint32_t)(r * 128);
        a_sw[i] = (uint32_t)((r & 7) << 4);
    }
    const uint32_t a_kc = (uint32_t)((lane >> 4) << 4);
    uint32_t b_rb[5], b_sw[5];
    #pragma unroll
    for (int j = 0; j < 5; j++) {
        const int n = wn * 80 + j * 16 + (lane & 7) + ((lane >> 4) << 3);
        b_rb[j] = (uint32_t)(n * 128 + SM_A_SZ);
        b_sw[j] = (uint32_t)((n & 7) << 4);
    }
    const uint32_t b_kc = (uint32_t)(((lane >> 3) & 1) << 4);

    float acc[2][10][4];
    #pragma unroll
    for (int i = 0; i < 2; i++)
        #pragma unroll
        for (int j = 0; j < 10; j++)
            #pragma unroll
            for (int q = 0; q < 4; q++) acc[i][j][q] = 0.0f;

    // ---- pipeline prologue: stages 0,1 ----
    #pragma unroll
    for (int st = 0; st < 2; st++) {
        const uint32_t sb = sBase + st * STAGE_SZ;
        #pragma unroll
        for (int j = 0; j < 4; j++) cp16(sb + aDst[j], aSrc[j] + st * 64);
        #pragma unroll
        for (int j = 0; j < 5; j++) cp16(sb + bDst[j], bSrc[j] + st * 64);
        CP_COMMIT();
    }

    int stage = 0;
    for (int c = 0; c < 48; c++) {
        CP_WAIT1();            // stage c resident
        __syncthreads();

        // prefetch stage c+2 (empty commit keeps group counting uniform)
        if (c + 2 < 48) {
            const int st = (stage + 2 >= 3) ? stage - 1 : stage + 2;
            const uint32_t sb = sBase + st * STAGE_SZ;
            #pragma unroll
            for (int j = 0; j < 4; j++) cp16(sb + aDst[j], aSrc[j] + (c + 2) * 64);
            #pragma unroll
            for (int j = 0; j < 5; j++) cp16(sb + bDst[j], bSrc[j] + (c + 2) * 64);
        }
        CP_COMMIT();

        // ---- compute chunk with fragment double-buffering ----
        const uint32_t stg = sBase + stage * STAGE_SZ;
        uint32_t af[2][2][4], bf[2][5][4];
        // load k-step 0 fragments
        #pragma unroll
        for (int i = 0; i < 2; i++) ldmx4(af[0][i], stg + a_rb[i] + (a_kc ^ a_sw[i]));
        #pragma unroll
        for (int j = 0; j < 5; j++) ldmx4(bf[0][j], stg + b_rb[j] + (b_kc ^ b_sw[j]));

        #pragma unroll
        for (int ks = 0; ks < 4; ks++) {
            const int cur = ks & 1, nxt = cur ^ 1;
            if (ks < 3) {
                const uint32_t k2 = (uint32_t)((ks + 1) * 32);
                #pragma unroll
                for (int i = 0; i < 2; i++)
                    ldmx4(af[nxt][i], stg + a_rb[i] + ((k2 + a_kc) ^ a_sw[i]));
                #pragma unroll
                for (int j = 0; j < 5; j++)
                    ldmx4(bf[nxt][j], stg + b_rb[j] + ((k2 + b_kc) ^ b_sw[j]));
            }
            #pragma unroll
            for (int i = 0; i < 2; i++)
                #pragma unroll
                for (int j = 0; j < 5; j++) {
                    mma16816(acc[i][2 * j],     af[cur][i], bf[cur][j][0], bf[cur][j][1]);
                    mma16816(acc[i][2 * j + 1], af[cur][i], bf[cur][j][2], bf[cur][j][3]);
                }
        }

        __syncthreads();       // all warps done with this stage before overwrite
        stage = (stage + 1 >= 3) ? 0 : stage + 1;
    }

    // ---- epilogue: add bias, store to g_logits ----
    #pragma unroll
    for (int j = 0; j < 10; j++) {
        const int col = n0 + wn * 80 + j * 8 + (lane & 3) * 2;
        const float2 bb = *(const float2*)(bias + col);
        #pragma unroll
        for (int i = 0; i < 2; i++) {
            const int r0 = m0 + wm * 32 + i * 16 + (lane >> 2);
            float2 v0 = { acc[i][j][0] + bb.x, acc[i][j][1] + bb.y };
            float2 v1 = { acc[i][j][2] + bb.x, acc[i][j][3] + bb.y };
            *(float2*)(&g_logits[(size_t)r0 * NCOLS + col])       = v0;
            *(float2*)(&g_logits[(size_t)(r0 + 8) * NCOLS + col]) = v1;
        }
    }
}

// ---------------------------------------------------------------------------
// Row kernel: argmax(l+gumbel) + softmax(l) + marginal + gather
// ---------------------------------------------------------------------------
__global__ __launch_bounds__(256)
void row_kernel(const float* __restrict__ gumbels,
                const int*   __restrict__ mask,
                const float* __restrict__ codevectors,
                float* __restrict__ out) {
    __shared__ float smarg[NCOLS];
    const int tid = threadIdx.x;
    for (int j = tid; j < NCOLS; j += 256) smarg[j] = 0.0f;
    __syncthreads();

    const int warp = tid >> 5;
    const int lane = tid & 31;
    const int g = warp & 1;
    const int nbase = blockIdx.x * 16 + (warp >> 1) * 4;

    for (int r = 0; r < 4; r++) {
        const int n = nbase + r;
        const float* lrow = g_logits + (size_t)n * NCOLS + g * VDIM;
        const float* grow = gumbels  + (size_t)n * NCOLS + g * VDIM;

        float l[10];
        float lmax = -1e30f, gmax = -1e30f;
        int gidx = 0;
        #pragma unroll
        for (int i = 0; i < 10; i++) {
            const int v = lane + 32 * i;
            l[i] = lrow[v];
            const float gv = l[i] + grow[v];
            lmax = fmaxf(lmax, l[i]);
            if (gv > gmax) { gmax = gv; gidx = v; }
        }
        #pragma unroll
        for (int o = 16; o > 0; o >>= 1)
            lmax = fmaxf(lmax, __shfl_xor_sync(0xffffffffu, lmax, o));
        #pragma unroll
        for (int o = 16; o > 0; o >>= 1) {
            const float ov = __shfl_xor_sync(0xffffffffu, gmax, o);
            const int   oi = __shfl_xor_sync(0xffffffffu, gidx, o);
            if (ov > gmax || (ov == gmax && oi < gidx)) { gmax = ov; gidx = oi; }
        }
        float e[10], s = 0.0f;
        #pragma unroll
        for (int i = 0; i < 10; i++) { e[i] = __expf(l[i] - lmax); s += e[i]; }
        #pragma unroll
        for (int o = 16; o > 0; o >>= 1)
            s += __shfl_xor_sync(0xffffffffu, s, o);
        const float inv = 1.0f / s;

        if (mask[n] != 0) {
            #pragma unroll
            for (int i = 0; i < 10; i++)
                atomicAdd(&smarg[g * VDIM + lane + 32 * i], e[i] * inv);
        }

        const float4* cb = (const float4*)(codevectors + (size_t)(g * VDIM + gidx) * DG);
        float4* o4 = (float4*)(out + (size_t)n * 256 + g * DG);
        o4[lane] = cb[lane];
    }

    __syncthreads();
    for (int j = tid; j < NCOLS; j += 256)
        atomicAdd(&g_marginal[j], smarg[j]);
}

// ---------------------------------------------------------------------------
// Finalize: perplexity. One CTA, 640 threads = 20 warps.
// ---------------------------------------------------------------------------
__global__ void finalize_kernel(const int* __restrict__ mask,
                                float* __restrict__ out, int out_size) {
    __shared__ float wsum[20];
    __shared__ float s_msum;
    const int tid  = threadIdx.x;
    const int warp = tid >> 5;
    const int lane = tid & 31;

    float c = 0.0f;
    for (int i = tid; i < NROWS; i += NCOLS) c += (mask[i] != 0) ? 1.0f : 0.0f;
    #pragma unroll
    for (int o = 16; o > 0; o >>= 1) c += __shfl_xor_sync(0xffffffffu, c, o);
    if (lane == 0) wsum[warp] = c;
    __syncthreads();
    if (tid == 0) {
        float s = 0.0f;
        #pragma unroll
        for (int w = 0; w < 20; w++) s += wsum[w];
        s_msum = s;
    }
    __syncthreads();

    const float p = g_marginal[tid] / s_msum;
    float h = p * logf(p + 1e-7f);
    #pragma unroll
    for (int o = 16; o > 0; o >>= 1) h += __shfl_xor_sync(0xffffffffu, h, o);
    __syncthreads();
    if (lane == 0) wsum[warp] = h;
    __syncthreads();

    if (tid == 0) {
        float e0 = 0.0f, e1 = 0.0f;
        #pragma unroll
        for (int w = 0; w < 10; w++)  e0 += wsum[w];
        #pragma unroll
        for (int w = 10; w < 20; w++) e1 += wsum[w];
        const float perp = expf(-e0) + expf(-e1);
        if (out_size > OUT_ELEMS) out[OUT_ELEMS] = perp;
    }
}

// ---------------------------------------------------------------------------
extern "C" void kernel_launch(void* const* d_in, const int* in_sizes, int n_in,
                              void* d_out, int out_size) {
    const float* X    = (const float*)d_in[0];
    const int*   mask = (const int*)  d_in[1];
    const float* W    = (const float*)d_in[2];
    const float* b    = (const float*)d_in[3];
    const float* cv   = (const float*)d_in[4];
    const float* gum  = (const float*)d_in[5];
    float* out = (float*)d_out;

    cudaFuncSetAttribute(gemm_kernel,
                         cudaFuncAttributeMaxDynamicSharedMemorySize, GEMM_SMEM);

    split_w_kernel<<<(KDIM * NCOLS + 255) / 256, 256>>>(W);
    split_x_kernel<<<NROWS * KDIM / (256 * 8), 256>>>(X);
    zero_marg_kernel<<<1, NCOLS>>>();
    dim3 ggrid(NCOLS / 160, NROWS / 128);   // (4, 128)
    gemm_kernel<<<ggrid, 256, GEMM_SMEM>>>(b);
    row_kernel<<<NROWS / 16, 256>>>(gum, mask, cv, out);
    finalize_kernel<<<1, NCOLS>>>(mask, out, out_size);
}